// round 9
// baseline (speedup 1.0000x reference)
#include <cuda_runtime.h>

// Scratch via __device__ globals (no allocations allowed).
__device__ float    g_part[8192];
__device__ unsigned g_count = 0;   // self-resetting ticket -> deterministic per call

// MUFU sqrt: single instruction, max rel err ~2^-23, sqrt(0)=0.
__device__ __forceinline__ float fsqrt_approx(float x) {
    float r;
    asm("sqrt.approx.f32 %0, %1;" : "=f"(r) : "f"(x));
    return r;
}

// Shapes fixed: [8,3,16,256,256] fp32 -> 384 planes of 256x256. Row = 64 float4.
// FULL-ROW WARPS: one warp covers a complete 256-wide row per step. Lane l holds
// u = row[q=l] and v = row[q=l+32] (two perfectly-coalesced 512B LDG.128 groups).
// Both circular x-wraps are intra-warp shuffles (q31.w->q32.x is v.x of lane 0,
// q63.w->q0.x is u.x of lane 0) -> zero scalar/divergent loads.
// Strip = 4 rows; all 5 rows (incl. circular down row) front-batched: 10
// independent LDG.128 in flight per thread. Down-row overlap (1.25x) hits L2.
// TV magnitude: sqrt((x[h,w]-x[h,w+1])^2 + (x[h,w]-x[h+1,w])^2), circular.
__global__ void __launch_bounds__(256, 4) tv_fused_kernel(const float4* __restrict__ in4,
                                                          float* __restrict__ out,
                                                          double inv_n) {
    const unsigned FULL = 0xFFFFFFFFu;
    const int lane = threadIdx.x & 31;
    const int wid  = threadIdx.x >> 5;
    const int gw   = blockIdx.x * 8 + wid;    // global warp id
    const int plane = gw >> 6;                // 64 strips per 256x256 plane
    const int h0    = (gw & 63) << 2;         // first row of this warp's 4-row strip

    const float4* __restrict__ p4 = in4 + ((long)plane << 14);  // 16384 float4/plane

    // ---- Load phase: 5 rows x 2 float4 per thread, all independent ----
    float4 u[5], v[5];
    #pragma unroll
    for (int i = 0; i < 5; i++) {
        const int rb = (((h0 + i) & 255) << 6);   // wraps only for the last strip
        u[i] = p4[rb + lane];
        v[i] = p4[rb + 32 + lane];
    }

    // ---- Compute phase ----
    float acc = 0.0f;
    #pragma unroll
    for (int i = 0; i < 4; i++) {
        // Right-neighbor of u.w: u.x of lane+1, except lane 31 -> v.x of lane 0.
        float su  = __shfl_down_sync(FULL, u[i].x, 1);
        float sv0 = __shfl_sync(FULL, v[i].x, 0);
        float nu  = (lane == 31) ? sv0 : su;
        // Right-neighbor of v.w: v.x of lane+1, except lane 31 -> u.x of lane 0 (row wrap).
        float sv  = __shfl_down_sync(FULL, v[i].x, 1);
        float su0 = __shfl_sync(FULL, u[i].x, 0);
        float nv  = (lane == 31) ? su0 : sv;

        #define TV_PROC(a, nxt, c)                                         \
        {                                                                  \
            float dx0 = a.x - a.y,   dy0 = a.x - c.x;                      \
            float dx1 = a.y - a.z,   dy1 = a.y - c.y;                      \
            float dx2 = a.z - a.w,   dy2 = a.z - c.z;                      \
            float dx3 = a.w - (nxt), dy3 = a.w - c.w;                      \
            acc += fsqrt_approx(fmaf(dx0, dx0, dy0 * dy0));                \
            acc += fsqrt_approx(fmaf(dx1, dx1, dy1 * dy1));                \
            acc += fsqrt_approx(fmaf(dx2, dx2, dy2 * dy2));                \
            acc += fsqrt_approx(fmaf(dx3, dx3, dy3 * dy3));                \
        }
        TV_PROC(u[i], nu, u[i + 1])
        TV_PROC(v[i], nv, v[i + 1])
        #undef TV_PROC
    }

    // Warp reduce (8 warps per block)
    #pragma unroll
    for (int o = 16; o > 0; o >>= 1)
        acc += __shfl_xor_sync(FULL, acc, o);

    __shared__ float warpsum[8];
    __shared__ bool  s_last;
    if (lane == 0) warpsum[wid] = acc;
    if (threadIdx.x == 0) s_last = false;
    __syncthreads();

    if (threadIdx.x == 0) {
        float bsum = warpsum[0] + warpsum[1] + warpsum[2] + warpsum[3]
                   + warpsum[4] + warpsum[5] + warpsum[6] + warpsum[7];
        g_part[blockIdx.x] = bsum;
        __threadfence();
        unsigned ticket = atomicAdd(&g_count, 1u);
        if (ticket == gridDim.x - 1) s_last = true;
    }
    __syncthreads();

    // Last block to arrive reduces all partials and writes the output.
    if (s_last) {
        double dsum = 0.0;
        for (int i = threadIdx.x; i < (int)gridDim.x; i += 256)
            dsum += (double)g_part[i];
        #pragma unroll
        for (int o = 16; o > 0; o >>= 1)
            dsum += __shfl_xor_sync(FULL, dsum, o);
        __shared__ double dws[8];
        if (lane == 0) dws[wid] = dsum;
        __syncthreads();
        if (threadIdx.x == 0) {
            double ssum = dws[0] + dws[1] + dws[2] + dws[3]
                        + dws[4] + dws[5] + dws[6] + dws[7];
            out[0] = (float)(ssum * inv_n);
            g_count = 0;   // reset for next (graph-replayed) call
        }
    }
}

extern "C" void kernel_launch(void* const* d_in, const int* in_sizes, int n_in,
                              void* d_out, int out_size) {
    const float4* in4 = (const float4*)d_in[0];
    float* out = (float*)d_out;
    const long long n = in_sizes[0];              // 25,165,824
    // 384 planes * 64 warps/plane / 8 warps/block = 3072 blocks of 256 threads
    const int threads = 256;
    const int blocks  = (int)(n / (threads * 32));  // 32 elems per thread -> 3072

    tv_fused_kernel<<<blocks, threads>>>(in4, out, 1.0 / (double)n);
}

// round 10
// speedup vs baseline: 1.2255x; 1.2255x over previous
#include <cuda_runtime.h>

// Scratch via __device__ globals (no allocations allowed).
__device__ float    g_part[8192];
__device__ unsigned g_count = 0;   // self-resetting ticket -> deterministic per call

// MUFU sqrt: single instruction, max rel err ~2^-23, sqrt(0)=0.
__device__ __forceinline__ float fsqrt_approx(float x) {
    float r;
    asm("sqrt.approx.f32 %0, %1;" : "=f"(r) : "f"(x));
    return r;
}

// Shapes fixed: [8,3,16,256,256] fp32 -> 384 planes of 256x256. Row = 64 float4.
// FULL-ROW WARPS + ROLLING WINDOW: one warp covers a complete 256-wide row per
// step (lane l holds u = row[q=l], v = row[q=l+32]; two 512B-coalesced LDG.128).
// Circular x-wraps are intra-warp shuffles only (q31.w->q32.x = v.x of lane 0;
// q63.w->q0.x = u.x of lane 0) -> zero divergent scalar loads.
// Strip = 8 rows (1.125x row-reuse traffic, absorbed by L2); rolling 1-row-ahead
// window keeps next-row loads in flight during current-row compute while the
// register footprint stays small -> no launch_bounds cap, occupancy stays high
// (R7/R9 showed occ>=80% beats deep per-thread batching here).
// TV magnitude: sqrt((x[h,w]-x[h,w+1])^2 + (x[h,w]-x[h+1,w])^2), circular.
__global__ void __launch_bounds__(256) tv_fused_kernel(const float4* __restrict__ in4,
                                                       float* __restrict__ out,
                                                       double inv_n) {
    const unsigned FULL = 0xFFFFFFFFu;
    const int lane = threadIdx.x & 31;
    const int wid  = threadIdx.x >> 5;
    const int gw   = blockIdx.x * 8 + wid;    // global warp id
    const int plane = gw >> 5;                // 32 strips per 256x256 plane
    const int h0    = (gw & 31) << 3;         // first row of this warp's 8-row strip

    const float4* __restrict__ p4 = in4 + ((long)plane << 14);  // 16384 float4/plane

    // Current row (h0)
    const int rb0 = h0 << 6;
    float4 uc = p4[rb0 + lane];
    float4 vc = p4[rb0 + 32 + lane];

    float acc = 0.0f;
    #pragma unroll
    for (int i = 0; i < 8; i++) {
        // Issue next-row loads FIRST (independent of current compute).
        const int rbn = (((h0 + i + 1) & 255) << 6);   // wraps only for last strip
        const float4 un = p4[rbn + lane];
        const float4 vn = p4[rbn + 32 + lane];

        // Circular x-neighbors via shuffle (all lanes execute both shuffles).
        const float su  = __shfl_down_sync(FULL, uc.x, 1);
        const float sv0 = __shfl_sync(FULL, vc.x, 0);
        const float nu  = (lane == 31) ? sv0 : su;
        const float sv  = __shfl_down_sync(FULL, vc.x, 1);
        const float su0 = __shfl_sync(FULL, uc.x, 0);
        const float nv  = (lane == 31) ? su0 : sv;

        #define TV_PROC(a, nxt, c)                                         \
        {                                                                  \
            float dx0 = a.x - a.y,   dy0 = a.x - c.x;                      \
            float dx1 = a.y - a.z,   dy1 = a.y - c.y;                      \
            float dx2 = a.z - a.w,   dy2 = a.z - c.z;                      \
            float dx3 = a.w - (nxt), dy3 = a.w - c.w;                      \
            acc += fsqrt_approx(fmaf(dx0, dx0, dy0 * dy0));                \
            acc += fsqrt_approx(fmaf(dx1, dx1, dy1 * dy1));                \
            acc += fsqrt_approx(fmaf(dx2, dx2, dy2 * dy2));                \
            acc += fsqrt_approx(fmaf(dx3, dx3, dy3 * dy3));                \
        }
        TV_PROC(uc, nu, un)
        TV_PROC(vc, nv, vn)
        #undef TV_PROC

        uc = un; vc = vn;
    }

    // Warp reduce (8 warps per block)
    #pragma unroll
    for (int o = 16; o > 0; o >>= 1)
        acc += __shfl_xor_sync(FULL, acc, o);

    __shared__ float warpsum[8];
    __shared__ bool  s_last;
    if (lane == 0) warpsum[wid] = acc;
    if (threadIdx.x == 0) s_last = false;
    __syncthreads();

    if (threadIdx.x == 0) {
        float bsum = warpsum[0] + warpsum[1] + warpsum[2] + warpsum[3]
                   + warpsum[4] + warpsum[5] + warpsum[6] + warpsum[7];
        g_part[blockIdx.x] = bsum;
        __threadfence();
        unsigned ticket = atomicAdd(&g_count, 1u);
        if (ticket == gridDim.x - 1) s_last = true;
    }
    __syncthreads();

    // Last block to arrive reduces all partials and writes the output.
    if (s_last) {
        double dsum = 0.0;
        for (int i = threadIdx.x; i < (int)gridDim.x; i += 256)
            dsum += (double)g_part[i];
        #pragma unroll
        for (int o = 16; o > 0; o >>= 1)
            dsum += __shfl_xor_sync(FULL, dsum, o);
        __shared__ double dws[8];
        if (lane == 0) dws[wid] = dsum;
        __syncthreads();
        if (threadIdx.x == 0) {
            double ssum = dws[0] + dws[1] + dws[2] + dws[3]
                        + dws[4] + dws[5] + dws[6] + dws[7];
            out[0] = (float)(ssum * inv_n);
            g_count = 0;   // reset for next (graph-replayed) call
        }
    }
}

extern "C" void kernel_launch(void* const* d_in, const int* in_sizes, int n_in,
                              void* d_out, int out_size) {
    const float4* in4 = (const float4*)d_in[0];
    float* out = (float*)d_out;
    const long long n = in_sizes[0];              // 25,165,824
    // 384 planes * 32 strips/plane = 12288 warps = 1536 blocks of 8 warps
    const int threads = 256;
    const int blocks  = (int)(n / (threads * 64));  // 64 elems per thread -> 1536

    tv_fused_kernel<<<blocks, threads>>>(in4, out, 1.0 / (double)n);
}